// round 15
// baseline (speedup 1.0000x reference)
#include <cuda_runtime.h>
#include <cstdint>

#define B_TOTAL 131072
#define NDIM 64
#define RANK 32
#define NPAIR (NDIM * NDIM)
#define MID_STRIDE (RANK*NDIM*RANK)
#define ROW_STRIDE (NDIM*RANK)

typedef unsigned long long ull;

__device__ float g_vbuf[B_TOTAL * RANK];
__device__ float g_A[NPAIR * RANK];
__device__ float g_Z[NPAIR * RANK];
__device__ float g_P1[NPAIR * RANK * RANK];
__device__ float g_P2[NPAIR * RANK * RANK];
__device__ int   g_perm[2][B_TOTAL];
__device__ int   g_hist[2][NPAIR];
__device__ int   g_base[2][NPAIR + 1];
__device__ int   g_cur[2][NPAIR];
__device__ int   g_sync;                 // software grid barrier; self-resetting

__device__ __forceinline__ int sniff64(const int32_t* raw) {
    unsigned int h = 0;
#pragma unroll
    for (int i = 0; i < 16; i++) h |= (unsigned int)raw[2 * i + 1];
    return (h == 0u) ? 1 : 0;
}
__device__ __forceinline__ int get_idx(const int32_t* raw, int e, int k, int is64) {
    int t;
    if (is64) t = (int)((const long long*)raw)[(long long)e * 8 + k];
    else      t = raw[e * 8 + k];
    return min(max(t, 0), NDIM - 1);
}
__device__ __forceinline__ ull pack2(float x, float y) {
    ull r; asm("mov.b64 %0,{%1,%2};" : "=l"(r) : "f"(x), "f"(y)); return r;
}
__device__ __forceinline__ void unpack2(ull v, float& x, float& y) {
    asm("mov.b64 {%0,%1},%2;" : "=f"(x), "=f"(y) : "l"(v));
}
__device__ __forceinline__ void fma2(ull& d, ull a, ull b) {
    asm("fma.rn.f32x2 %0,%1,%2,%0;" : "+l"(d) : "l"(a), "l"(b));
}

// ============================================================================
// kHS: histogram + scan FUSED (one launch).
//   blocks [0,16): histogram (1024 thr x 8 elems), arrive on g_sync
//   blocks 16,17 : spin until all 16 arrived, then scan step m = b-16
// 18 blocks are all resident at launch (<< 148 SMs) -> no deadlock.
// g_sync returns to 0 by kernel end (each scan block subtracts 8).
// ============================================================================
__global__ __launch_bounds__(1024)
void kHS(const int32_t* __restrict__ raw) {
    __shared__ int sh[1024];
    const int b = blockIdx.x, t = threadIdx.x;

    if (b < 16) {
        const int is64 = sniff64(raw);
#pragma unroll
        for (int i = 0; i < 8; i++) {
            const int e = b * 8192 + i * 1024 + t;
            int k0 = get_idx(raw, e, 2, is64) * NDIM + get_idx(raw, e, 3, is64);
            int k1 = get_idx(raw, e, 4, is64) * NDIM + get_idx(raw, e, 5, is64);
            atomicAdd(&g_hist[0][k0], 1);
            atomicAdd(&g_hist[1][k1], 1);
        }
        __syncthreads();
        if (t == 0) { __threadfence(); atomicAdd(&g_sync, 1); }
        return;
    }

    // ---- scan block ----
    const int m = b - 16;
    if (t == 0) { while (atomicAdd(&g_sync, 0) < 16) { } }
    __syncthreads();
    __threadfence();

    int4 v4 = reinterpret_cast<const int4*>(g_hist[m])[t];
    int vals[4] = {v4.x, v4.y, v4.z, v4.w};
    int s = vals[0] + vals[1] + vals[2] + vals[3];
    sh[t] = s;
    __syncthreads();
    for (int off = 1; off < 1024; off <<= 1) {
        int u = (t >= off) ? sh[t - off] : 0;
        __syncthreads();
        sh[t] += u;
        __syncthreads();
    }
    int run = sh[t] - s;
#pragma unroll
    for (int i = 0; i < 4; i++) {
        int bin = t * 4 + i;
        g_base[m][bin] = run;
        g_cur[m][bin]  = run;
        g_hist[m][bin] = 0;              // ready for next graph replay
        run += vals[i];
    }
    if (t == 1023) {
        g_base[m][NPAIR] = B_TOTAL;
        atomicSub(&g_sync, 8);           // 2 blocks x 8 -> counter back to 0
    }
}

// ============================================================================
// kPre: scatter + A + P1 fold — only what step0 needs
//   [0,256)    scatter        [256,320) A fold       [320,832) P1 fold
// ============================================================================
__global__ __launch_bounds__(256)
void kPre(const int32_t* __restrict__ raw,
          const float* __restrict__ core0,
          const float* __restrict__ mids) {
    __shared__ float S[RANK * 34];
    const int b = blockIdx.x, tid = threadIdx.x;
    const int warp = tid >> 5, lane = tid & 31;

    if (b < 256) {
        const int is64 = sniff64(raw);
#pragma unroll
        for (int i = 0; i < 2; i++) {
            const int e = b * 512 + i * 256 + tid;
            int k0 = get_idx(raw, e, 2, is64) * NDIM + get_idx(raw, e, 3, is64);
            int k1 = get_idx(raw, e, 4, is64) * NDIM + get_idx(raw, e, 5, is64);
            g_perm[0][atomicAdd(&g_cur[0][k0], 1)] = e;
            g_perm[1][atomicAdd(&g_cur[1][k1], 1)] = e;
        }
    } else if (b < 320) {
        const int j0 = b - 256;
        if (tid < RANK) S[tid] = core0[j0 * RANK + tid];
        __syncthreads();
#pragma unroll
        for (int t = 0; t < 8; t++) {
            const int j1 = warp * 8 + t;
            float acc = 0.0f;
#pragma unroll
            for (int r = 0; r < RANK; r++)
                acc = fmaf(S[r], mids[r * ROW_STRIDE + j1 * RANK + lane], acc);
            g_A[(j0 * NDIM + j1) * RANK + lane] = acc;
        }
    } else {
        // P1[ja,jb][r][s] = sum_m M1[r,ja,m] * M2[m,jb,s]
        const int x = b - 320;                    // 0..511
        const int ja = x >> 3;
        const float* Ma = mids + 1 * MID_STRIDE;
        const float* Mb = mids + 2 * MID_STRIDE;

        for (int i = tid; i < RANK * RANK; i += 256) {
            int r = i >> 5, m = i & 31;
            S[m * 34 + r] = Ma[r * ROW_STRIDE + ja * RANK + m];
        }
        __syncthreads();

        const int jb = (x & 7) * 8 + warp;
        float m2[RANK];
#pragma unroll
        for (int m = 0; m < RANK; m++)
            m2[m] = Mb[m * ROW_STRIDE + jb * RANK + lane];

        ull acc2[16];
#pragma unroll
        for (int q = 0; q < 16; q++) acc2[q] = 0ull;
#pragma unroll
        for (int m = 0; m < RANK; m++) {
            const ull dup = pack2(m2[m], m2[m]);
            const ull* Sp = reinterpret_cast<const ull*>(S + m * 34);
#pragma unroll
            for (int rp = 0; rp < 16; rp++) fma2(acc2[rp], Sp[rp], dup);
        }
        float* Pp = g_P1 + (ja * NDIM + jb) * (RANK * RANK);
#pragma unroll
        for (int rp = 0; rp < 16; rp++) {
            float a, c;
            unpack2(acc2[rp], a, c);
            Pp[(2 * rp) * RANK + lane]     = a;
            Pp[(2 * rp + 1) * RANK + lane] = c;
        }
    }
}

// ============================================================================
// step0m: step0 bins FIRST, then P2/Z folds (R12 ordering — proven fastest).
//   [0,4096)      step0 bins    [4096,8192) P2 fold    [8192,8704) Z fold
// ============================================================================
__global__ __launch_bounds__(32)
void step0m(const int32_t* __restrict__ raw,
            const float* __restrict__ mids,
            const float* __restrict__ cl,
            const float* __restrict__ P1tab) {
    __shared__ __align__(16) float slice[RANK * RANK];
    __shared__ float st[RANK * 33];
    const int lane = threadIdx.x;
    const int b = blockIdx.x;

    if (b < 4096) {
        // ---------------- step0 bin (frozen inner loop) ----------------
        const int bin = b;
        const int lo = g_base[0][bin], hi = g_base[0][bin + 1];
        if (lo == hi) return;

        const float4* src4 = reinterpret_cast<const float4*>(P1tab + bin * (RANK * RANK));
        float4* dst4 = reinterpret_cast<float4*>(slice);
#pragma unroll
        for (int i = 0; i < 8; i++) dst4[i * 32 + lane] = src4[i * 32 + lane];

        const int is64 = sniff64(raw);
        __syncwarp();

        for (int base = lo; base < hi; base += 32) {
            const int n = min(32, hi - base);
            int e = 0, rowidx = 0;
            if (lane < n) {
                e = g_perm[0][base + lane];
                rowidx = get_idx(raw, e, 0, is64) * NDIM + get_idx(raw, e, 1, is64);
            }
            __syncwarp();
            for (int w = 0; w < n; w++) {
                int re = __shfl_sync(0xffffffffu, rowidx, w);
                st[w * 33 + lane] = g_A[re * RANK + lane];
            }
            __syncwarp();

            ull acc[16];
#pragma unroll
            for (int q = 0; q < 16; q++) acc[q] = 0ull;
#pragma unroll 8
            for (int r = 0; r < RANK; r++) {
                float vr = st[lane * 33 + r];
                ull v2 = pack2(vr, vr);
                const ulonglong2* sp = reinterpret_cast<const ulonglong2*>(slice + r * RANK);
#pragma unroll
                for (int q = 0; q < 8; q++) {
                    ulonglong2 z = sp[q];
                    fma2(acc[2 * q],     z.x, v2);
                    fma2(acc[2 * q + 1], z.y, v2);
                }
            }

            __syncwarp();
#pragma unroll
            for (int q = 0; q < 16; q++) {
                float a, c;
                unpack2(acc[q], a, c);
                st[lane * 33 + 2 * q]     = a;
                st[lane * 33 + 2 * q + 1] = c;
            }
            __syncwarp();
            for (int w = 0; w < n; w++) {
                int ee = __shfl_sync(0xffffffffu, e, w);
                g_vbuf[ee * RANK + lane] = st[w * 33 + lane];
            }
        }
    } else if (b < 8192) {
        // ---------------- P2 fold ----------------
        const int f = b - 4096;
        const int ja = f >> 6, jb = f & 63;
        const float* Ma = mids + 3 * MID_STRIDE;
        const float* Mb = mids + 4 * MID_STRIDE;

        for (int i = lane; i < RANK * RANK; i += 32) {
            int r = i >> 5, m = i & 31;
            st[m * 33 + r] = Ma[r * ROW_STRIDE + ja * RANK + m];
        }
        __syncwarp();

        float m2[RANK];
#pragma unroll
        for (int m = 0; m < RANK; m++)
            m2[m] = Mb[m * ROW_STRIDE + jb * RANK + lane];

        ull acc2[16];
#pragma unroll
        for (int q = 0; q < 16; q++) acc2[q] = 0ull;
#pragma unroll
        for (int m = 0; m < RANK; m++) {
            const ull dup = pack2(m2[m], m2[m]);
            const float* Sr = st + m * 33;
#pragma unroll
            for (int rp = 0; rp < 16; rp++) {
                ull sv = pack2(Sr[2 * rp], Sr[2 * rp + 1]);
                fma2(acc2[rp], sv, dup);
            }
        }
        float* Pp = g_P2 + (ja * NDIM + jb) * (RANK * RANK);
#pragma unroll
        for (int rp = 0; rp < 16; rp++) {
            float a, c;
            unpack2(acc2[rp], a, c);
            Pp[(2 * rp) * RANK + lane]     = a;
            Pp[(2 * rp + 1) * RANK + lane] = c;
        }
    } else {
        // ---------------- Z fold ----------------
        const int z = b - 8192;
        const int j6 = z >> 3, grp = z & 7;
        const float* M5 = mids + 5 * MID_STRIDE;

        for (int i = lane; i < RANK * RANK; i += 32) {
            int r = i >> 5, s = i & 31;
            st[s * 33 + r] = M5[r * ROW_STRIDE + j6 * RANK + s];
        }
        __syncwarp();

#pragma unroll
        for (int t = 0; t < 8; t++) {
            const int j7 = grp * 8 + t;
            float acc = 0.0f;
#pragma unroll
            for (int s = 0; s < RANK; s++)
                acc = fmaf(cl[s * NDIM + j7], st[s * 33 + lane], acc);
            g_Z[(j6 * NDIM + j7) * RANK + lane] = acc;
        }
    }
}

// ============================================================================
// step1: frozen R12 shape (grid 4096, block 32)
// ============================================================================
__global__ __launch_bounds__(32)
void step1_kernel(const int32_t* __restrict__ raw,
                  const float* __restrict__ P2tab, float* __restrict__ out) {
    __shared__ __align__(16) float slice[RANK * RANK];
    __shared__ float st[RANK * 33];
    const int lane = threadIdx.x;
    const int bin = blockIdx.x;
    const int lo = g_base[1][bin], hi = g_base[1][bin + 1];
    if (lo == hi) return;

    const float4* src4 = reinterpret_cast<const float4*>(P2tab + bin * (RANK * RANK));
    float4* dst4 = reinterpret_cast<float4*>(slice);
#pragma unroll
    for (int i = 0; i < 8; i++) dst4[i * 32 + lane] = src4[i * 32 + lane];

    const int is64 = sniff64(raw);
    __syncwarp();

    for (int base = lo; base < hi; base += 32) {
        const int n = min(32, hi - base);
        int e = 0;
        if (lane < n) e = g_perm[1][base + lane];
        __syncwarp();
        for (int w = 0; w < n; w++) {
            int re = __shfl_sync(0xffffffffu, e, w);
            st[w * 33 + lane] = g_vbuf[re * RANK + lane];
        }
        __syncwarp();

        ull acc[16];
#pragma unroll
        for (int q = 0; q < 16; q++) acc[q] = 0ull;
#pragma unroll 8
        for (int r = 0; r < RANK; r++) {
            float vr = st[lane * 33 + r];
            ull v2 = pack2(vr, vr);
            const ulonglong2* sp = reinterpret_cast<const ulonglong2*>(slice + r * RANK);
#pragma unroll
            for (int q = 0; q < 8; q++) {
                ulonglong2 z = sp[q];
                fma2(acc[2 * q],     z.x, v2);
                fma2(acc[2 * q + 1], z.y, v2);
            }
        }

        if (lane < n) {
            int zrow = get_idx(raw, e, 6, is64) * NDIM + get_idx(raw, e, 7, is64);
            const ull* zp = reinterpret_cast<const ull*>(g_Z + zrow * RANK);
            ull d = 0ull;
#pragma unroll
            for (int q = 0; q < 16; q++) fma2(d, acc[q], zp[q]);
            float a, c;
            unpack2(d, a, c);
            out[e] = a + c;
        }
    }
}

extern "C" void kernel_launch(void* const* d_in, const int* in_sizes, int n_in,
                              void* d_out, int out_size) {
    const int32_t* indices  = (const int32_t*)d_in[0];
    const float*   core0    = (const float*)d_in[1];
    const float*   coresmid = (const float*)d_in[2];
    const float*   corelast = (const float*)d_in[3];
    float*         out      = (float*)d_out;

    float* p1;  cudaGetSymbolAddress((void**)&p1, g_P1);
    float* p2;  cudaGetSymbolAddress((void**)&p2, g_P2);

    kHS<<<18, 1024>>>(indices);
    kPre<<<832, 256>>>(indices, core0, coresmid);
    step0m<<<8704, 32>>>(indices, coresmid, corelast, p1);
    step1_kernel<<<4096, 32>>>(indices, p2, out);
}

// round 16
// speedup vs baseline: 1.0570x; 1.0570x over previous
#include <cuda_runtime.h>
#include <cstdint>

#define B_TOTAL 131072
#define NDIM 64
#define RANK 32
#define NPAIR (NDIM * NDIM)
#define MID_STRIDE (RANK*NDIM*RANK)
#define ROW_STRIDE (NDIM*RANK)

typedef unsigned long long ull;

__device__ float g_vbuf[B_TOTAL * RANK];
__device__ float g_A[NPAIR * RANK];
__device__ float g_Z[NPAIR * RANK];
__device__ float g_P1[NPAIR * RANK * RANK];
__device__ float g_P2[NPAIR * RANK * RANK];
__device__ int   g_perm[2][B_TOTAL];
__device__ int   g_hist[2][NPAIR];
__device__ int   g_base[2][NPAIR + 1];
__device__ int   g_cur[2][NPAIR];

__device__ __forceinline__ int sniff64(const int32_t* raw) {
    unsigned int h = 0;
#pragma unroll
    for (int i = 0; i < 16; i++) h |= (unsigned int)raw[2 * i + 1];
    return (h == 0u) ? 1 : 0;
}
__device__ __forceinline__ int get_idx(const int32_t* raw, int e, int k, int is64) {
    int t;
    if (is64) t = (int)((const long long*)raw)[(long long)e * 8 + k];
    else      t = raw[e * 8 + k];
    return min(max(t, 0), NDIM - 1);
}
__device__ __forceinline__ ull pack2(float x, float y) {
    ull r; asm("mov.b64 %0,{%1,%2};" : "=l"(r) : "f"(x), "f"(y)); return r;
}
__device__ __forceinline__ void unpack2(ull v, float& x, float& y) {
    asm("mov.b64 {%0,%1},%2;" : "=f"(x), "=f"(y) : "l"(v));
}
__device__ __forceinline__ void fma2(ull& d, ull a, ull b) {
    asm("fma.rn.f32x2 %0,%1,%2,%0;" : "+l"(d) : "l"(a), "l"(b));
}

// ============================================================================
// kH: histogram of pair keys (R12 verbatim: 64 blocks x 256)
// ============================================================================
__global__ __launch_bounds__(256)
void kH_hist(const int32_t* __restrict__ raw) {
    const int b = blockIdx.x, tid = threadIdx.x;
    const int is64 = sniff64(raw);
#pragma unroll
    for (int i = 0; i < 8; i++) {
        const int e = b * 2048 + i * 256 + tid;
        int k0 = get_idx(raw, e, 2, is64) * NDIM + get_idx(raw, e, 3, is64);
        int k1 = get_idx(raw, e, 4, is64) * NDIM + get_idx(raw, e, 5, is64);
        atomicAdd(&g_hist[0][k0], 1);
        atomicAdd(&g_hist[1][k1], 1);
    }
}

// ============================================================================
// k2: exclusive scan; init cursors; reset hist for next graph replay
// ============================================================================
__global__ __launch_bounds__(1024)
void k2_scan() {
    __shared__ int sh[1024];
    const int m = blockIdx.x, t = threadIdx.x;
    int4 v4 = reinterpret_cast<const int4*>(g_hist[m])[t];
    int vals[4] = {v4.x, v4.y, v4.z, v4.w};
    int s = vals[0] + vals[1] + vals[2] + vals[3];
    sh[t] = s;
    __syncthreads();
    for (int off = 1; off < 1024; off <<= 1) {
        int u = (t >= off) ? sh[t - off] : 0;
        __syncthreads();
        sh[t] += u;
        __syncthreads();
    }
    int run = sh[t] - s;
#pragma unroll
    for (int i = 0; i < 4; i++) {
        int bin = t * 4 + i;
        g_base[m][bin] = run;
        g_cur[m][bin]  = run;
        g_hist[m][bin] = 0;
        run += vals[i];
    }
    if (t == 1023) g_base[m][NPAIR] = B_TOTAL;
}

// ============================================================================
// kPre: scatter + A + P1 fold + Z fold (Z moved here from step0m's tail —
// kPre is scatter-latency-bound with idle fma slots; Z is needed only by step1).
//   [0,128)    scatter     [128,192) A     [192,704) P1     [704,768) Z
// ============================================================================
__global__ __launch_bounds__(256)
void kPre(const int32_t* __restrict__ raw,
          const float* __restrict__ core0,
          const float* __restrict__ mids,
          const float* __restrict__ cl) {
    __shared__ float S[RANK * 34];
    const int b = blockIdx.x, tid = threadIdx.x;
    const int warp = tid >> 5, lane = tid & 31;

    if (b < 128) {
        const int is64 = sniff64(raw);
#pragma unroll
        for (int i = 0; i < 4; i++) {
            const int e = b * 1024 + i * 256 + tid;
            int k0 = get_idx(raw, e, 2, is64) * NDIM + get_idx(raw, e, 3, is64);
            int k1 = get_idx(raw, e, 4, is64) * NDIM + get_idx(raw, e, 5, is64);
            g_perm[0][atomicAdd(&g_cur[0][k0], 1)] = e;
            g_perm[1][atomicAdd(&g_cur[1][k1], 1)] = e;
        }
    } else if (b < 192) {
        const int j0 = b - 128;
        if (tid < RANK) S[tid] = core0[j0 * RANK + tid];
        __syncthreads();
#pragma unroll
        for (int t = 0; t < 8; t++) {
            const int j1 = warp * 8 + t;
            float acc = 0.0f;
#pragma unroll
            for (int r = 0; r < RANK; r++)
                acc = fmaf(S[r], mids[r * ROW_STRIDE + j1 * RANK + lane], acc);
            g_A[(j0 * NDIM + j1) * RANK + lane] = acc;
        }
    } else if (b < 704) {
        // P1[ja,jb][r][s] = sum_m M1[r,ja,m] * M2[m,jb,s]
        const int x = b - 192;                    // 0..511
        const int ja = x >> 3;
        const float* Ma = mids + 1 * MID_STRIDE;
        const float* Mb = mids + 2 * MID_STRIDE;

        for (int i = tid; i < RANK * RANK; i += 256) {
            int r = i >> 5, m = i & 31;
            S[m * 34 + r] = Ma[r * ROW_STRIDE + ja * RANK + m];
        }
        __syncthreads();

        const int jb = (x & 7) * 8 + warp;
        float m2[RANK];
#pragma unroll
        for (int m = 0; m < RANK; m++)
            m2[m] = Mb[m * ROW_STRIDE + jb * RANK + lane];

        ull acc2[16];
#pragma unroll
        for (int q = 0; q < 16; q++) acc2[q] = 0ull;
#pragma unroll
        for (int m = 0; m < RANK; m++) {
            const ull dup = pack2(m2[m], m2[m]);
            const ull* Sp = reinterpret_cast<const ull*>(S + m * 34);
#pragma unroll
            for (int rp = 0; rp < 16; rp++) fma2(acc2[rp], Sp[rp], dup);
        }
        float* Pp = g_P1 + (ja * NDIM + jb) * (RANK * RANK);
#pragma unroll
        for (int rp = 0; rp < 16; rp++) {
            float a, c;
            unpack2(acc2[rp], a, c);
            Pp[(2 * rp) * RANK + lane]     = a;
            Pp[(2 * rp + 1) * RANK + lane] = c;
        }
    } else {
        // Z fold (R11 kBig style): j6 = b-704; warp covers 8 j7 values
        const int j6 = b - 704;
        const float* M5 = mids + 5 * MID_STRIDE;
        for (int i = tid; i < RANK * RANK; i += 256) {
            int r = i >> 5, s = i & 31;
            S[s * 34 + r] = M5[r * ROW_STRIDE + j6 * RANK + s];
        }
        __syncthreads();
#pragma unroll
        for (int t = 0; t < 8; t++) {
            const int j7 = warp * 8 + t;
            float acc = 0.0f;
#pragma unroll
            for (int s = 0; s < RANK; s++)
                acc = fmaf(cl[s * NDIM + j7], S[s * 34 + lane], acc);
            g_Z[(j6 * NDIM + j7) * RANK + lane] = acc;
        }
    }
}

// ============================================================================
// step0m: step0 bins FIRST, then P2 fold (R12 ordering; Z removed from tail).
//   [0,4096) step0 bins      [4096,8192) P2 fold
// ============================================================================
__global__ __launch_bounds__(32)
void step0m(const int32_t* __restrict__ raw,
            const float* __restrict__ mids,
            const float* __restrict__ P1tab) {
    __shared__ __align__(16) float slice[RANK * RANK];
    __shared__ float st[RANK * 33];
    const int lane = threadIdx.x;
    const int b = blockIdx.x;

    if (b < 4096) {
        // ---------------- step0 bin (frozen inner loop) ----------------
        const int bin = b;
        const int lo = g_base[0][bin], hi = g_base[0][bin + 1];
        if (lo == hi) return;

        const float4* src4 = reinterpret_cast<const float4*>(P1tab + bin * (RANK * RANK));
        float4* dst4 = reinterpret_cast<float4*>(slice);
#pragma unroll
        for (int i = 0; i < 8; i++) dst4[i * 32 + lane] = src4[i * 32 + lane];

        const int is64 = sniff64(raw);
        __syncwarp();

        for (int base = lo; base < hi; base += 32) {
            const int n = min(32, hi - base);
            int e = 0, rowidx = 0;
            if (lane < n) {
                e = g_perm[0][base + lane];
                rowidx = get_idx(raw, e, 0, is64) * NDIM + get_idx(raw, e, 1, is64);
            }
            __syncwarp();
            for (int w = 0; w < n; w++) {
                int re = __shfl_sync(0xffffffffu, rowidx, w);
                st[w * 33 + lane] = g_A[re * RANK + lane];
            }
            __syncwarp();

            ull acc[16];
#pragma unroll
            for (int q = 0; q < 16; q++) acc[q] = 0ull;
#pragma unroll 8
            for (int r = 0; r < RANK; r++) {
                float vr = st[lane * 33 + r];
                ull v2 = pack2(vr, vr);
                const ulonglong2* sp = reinterpret_cast<const ulonglong2*>(slice + r * RANK);
#pragma unroll
                for (int q = 0; q < 8; q++) {
                    ulonglong2 z = sp[q];
                    fma2(acc[2 * q],     z.x, v2);
                    fma2(acc[2 * q + 1], z.y, v2);
                }
            }

            __syncwarp();
#pragma unroll
            for (int q = 0; q < 16; q++) {
                float a, c;
                unpack2(acc[q], a, c);
                st[lane * 33 + 2 * q]     = a;
                st[lane * 33 + 2 * q + 1] = c;
            }
            __syncwarp();
            for (int w = 0; w < n; w++) {
                int ee = __shfl_sync(0xffffffffu, e, w);
                g_vbuf[ee * RANK + lane] = st[w * 33 + lane];
            }
        }
    } else {
        // ---------------- P2 fold ----------------
        const int f = b - 4096;
        const int ja = f >> 6, jb = f & 63;
        const float* Ma = mids + 3 * MID_STRIDE;
        const float* Mb = mids + 4 * MID_STRIDE;

        for (int i = lane; i < RANK * RANK; i += 32) {
            int r = i >> 5, m = i & 31;
            st[m * 33 + r] = Ma[r * ROW_STRIDE + ja * RANK + m];
        }
        __syncwarp();

        float m2[RANK];
#pragma unroll
        for (int m = 0; m < RANK; m++)
            m2[m] = Mb[m * ROW_STRIDE + jb * RANK + lane];

        ull acc2[16];
#pragma unroll
        for (int q = 0; q < 16; q++) acc2[q] = 0ull;
#pragma unroll
        for (int m = 0; m < RANK; m++) {
            const ull dup = pack2(m2[m], m2[m]);
            const float* Sr = st + m * 33;
#pragma unroll
            for (int rp = 0; rp < 16; rp++) {
                ull sv = pack2(Sr[2 * rp], Sr[2 * rp + 1]);
                fma2(acc2[rp], sv, dup);
            }
        }
        float* Pp = g_P2 + (ja * NDIM + jb) * (RANK * RANK);
#pragma unroll
        for (int rp = 0; rp < 16; rp++) {
            float a, c;
            unpack2(acc2[rp], a, c);
            Pp[(2 * rp) * RANK + lane]     = a;
            Pp[(2 * rp + 1) * RANK + lane] = c;
        }
    }
}

// ============================================================================
// step1: frozen R12 shape (grid 4096, block 32)
// ============================================================================
__global__ __launch_bounds__(32)
void step1_kernel(const int32_t* __restrict__ raw,
                  const float* __restrict__ P2tab, float* __restrict__ out) {
    __shared__ __align__(16) float slice[RANK * RANK];
    __shared__ float st[RANK * 33];
    const int lane = threadIdx.x;
    const int bin = blockIdx.x;
    const int lo = g_base[1][bin], hi = g_base[1][bin + 1];
    if (lo == hi) return;

    const float4* src4 = reinterpret_cast<const float4*>(P2tab + bin * (RANK * RANK));
    float4* dst4 = reinterpret_cast<float4*>(slice);
#pragma unroll
    for (int i = 0; i < 8; i++) dst4[i * 32 + lane] = src4[i * 32 + lane];

    const int is64 = sniff64(raw);
    __syncwarp();

    for (int base = lo; base < hi; base += 32) {
        const int n = min(32, hi - base);
        int e = 0;
        if (lane < n) e = g_perm[1][base + lane];
        __syncwarp();
        for (int w = 0; w < n; w++) {
            int re = __shfl_sync(0xffffffffu, e, w);
            st[w * 33 + lane] = g_vbuf[re * RANK + lane];
        }
        __syncwarp();

        ull acc[16];
#pragma unroll
        for (int q = 0; q < 16; q++) acc[q] = 0ull;
#pragma unroll 8
        for (int r = 0; r < RANK; r++) {
            float vr = st[lane * 33 + r];
            ull v2 = pack2(vr, vr);
            const ulonglong2* sp = reinterpret_cast<const ulonglong2*>(slice + r * RANK);
#pragma unroll
            for (int q = 0; q < 8; q++) {
                ulonglong2 z = sp[q];
                fma2(acc[2 * q],     z.x, v2);
                fma2(acc[2 * q + 1], z.y, v2);
            }
        }

        if (lane < n) {
            int zrow = get_idx(raw, e, 6, is64) * NDIM + get_idx(raw, e, 7, is64);
            const ull* zp = reinterpret_cast<const ull*>(g_Z + zrow * RANK);
            ull d = 0ull;
#pragma unroll
            for (int q = 0; q < 16; q++) fma2(d, acc[q], zp[q]);
            float a, c;
            unpack2(d, a, c);
            out[e] = a + c;
        }
    }
}

extern "C" void kernel_launch(void* const* d_in, const int* in_sizes, int n_in,
                              void* d_out, int out_size) {
    const int32_t* indices  = (const int32_t*)d_in[0];
    const float*   core0    = (const float*)d_in[1];
    const float*   coresmid = (const float*)d_in[2];
    const float*   corelast = (const float*)d_in[3];
    float*         out      = (float*)d_out;

    float* p1;  cudaGetSymbolAddress((void**)&p1, g_P1);
    float* p2;  cudaGetSymbolAddress((void**)&p2, g_P2);

    kH_hist<<<64, 256>>>(indices);
    k2_scan<<<2, 1024>>>();
    kPre<<<768, 256>>>(indices, core0, coresmid, corelast);
    step0m<<<8192, 32>>>(indices, coresmid, p1);
    step1_kernel<<<4096, 32>>>(indices, p2, out);
}

// round 17
// speedup vs baseline: 1.0869x; 1.0282x over previous
#include <cuda_runtime.h>
#include <cstdint>

#define B_TOTAL 131072
#define NDIM 64
#define RANK 32
#define NPAIR (NDIM * NDIM)
#define MID_STRIDE (RANK*NDIM*RANK)
#define ROW_STRIDE (NDIM*RANK)

typedef unsigned long long ull;

__device__ float g_vbuf[B_TOTAL * RANK];
__device__ float g_A[NPAIR * RANK];
__device__ float g_Z[NPAIR * RANK];
__device__ float g_P1[NPAIR * RANK * RANK];
__device__ float g_P2[NPAIR * RANK * RANK];
__device__ int   g_perm[2][B_TOTAL];
__device__ int   g_pos1[B_TOTAL];        // inverse of perm1: element -> slot
__device__ int   g_hist[2][NPAIR];
__device__ int   g_base[2][NPAIR + 1];
__device__ int   g_cur[2][NPAIR];

__device__ __forceinline__ int sniff64(const int32_t* raw) {
    unsigned int h = 0;
#pragma unroll
    for (int i = 0; i < 16; i++) h |= (unsigned int)raw[2 * i + 1];
    return (h == 0u) ? 1 : 0;
}
__device__ __forceinline__ int get_idx(const int32_t* raw, int e, int k, int is64) {
    int t;
    if (is64) t = (int)((const long long*)raw)[(long long)e * 8 + k];
    else      t = raw[e * 8 + k];
    return min(max(t, 0), NDIM - 1);
}
__device__ __forceinline__ ull pack2(float x, float y) {
    ull r; asm("mov.b64 %0,{%1,%2};" : "=l"(r) : "f"(x), "f"(y)); return r;
}
__device__ __forceinline__ void unpack2(ull v, float& x, float& y) {
    asm("mov.b64 {%0,%1},%2;" : "=f"(x), "=f"(y) : "l"(v));
}
__device__ __forceinline__ void fma2(ull& d, ull a, ull b) {
    asm("fma.rn.f32x2 %0,%1,%2,%0;" : "+l"(d) : "l"(a), "l"(b));
}

// ============================================================================
// kH: histogram of pair keys (64 blocks x 256)
// ============================================================================
__global__ __launch_bounds__(256)
void kH_hist(const int32_t* __restrict__ raw) {
    const int b = blockIdx.x, tid = threadIdx.x;
    const int is64 = sniff64(raw);
#pragma unroll
    for (int i = 0; i < 8; i++) {
        const int e = b * 2048 + i * 256 + tid;
        int k0 = get_idx(raw, e, 2, is64) * NDIM + get_idx(raw, e, 3, is64);
        int k1 = get_idx(raw, e, 4, is64) * NDIM + get_idx(raw, e, 5, is64);
        atomicAdd(&g_hist[0][k0], 1);
        atomicAdd(&g_hist[1][k1], 1);
    }
}

// ============================================================================
// k2: exclusive scan; init cursors; reset hist for next graph replay
// ============================================================================
__global__ __launch_bounds__(1024)
void k2_scan() {
    __shared__ int sh[1024];
    const int m = blockIdx.x, t = threadIdx.x;
    int4 v4 = reinterpret_cast<const int4*>(g_hist[m])[t];
    int vals[4] = {v4.x, v4.y, v4.z, v4.w};
    int s = vals[0] + vals[1] + vals[2] + vals[3];
    sh[t] = s;
    __syncthreads();
    for (int off = 1; off < 1024; off <<= 1) {
        int u = (t >= off) ? sh[t - off] : 0;
        __syncthreads();
        sh[t] += u;
        __syncthreads();
    }
    int run = sh[t] - s;
#pragma unroll
    for (int i = 0; i < 4; i++) {
        int bin = t * 4 + i;
        g_base[m][bin] = run;
        g_cur[m][bin]  = run;
        g_hist[m][bin] = 0;
        run += vals[i];
    }
    if (t == 1023) g_base[m][NPAIR] = B_TOTAL;
}

// ============================================================================
// kPre: scatter (+pos1 inverse) + A + P1 fold + Z fold
//   [0,128)    scatter     [128,192) A     [192,704) P1     [704,768) Z
// ============================================================================
__global__ __launch_bounds__(256)
void kPre(const int32_t* __restrict__ raw,
          const float* __restrict__ core0,
          const float* __restrict__ mids,
          const float* __restrict__ cl) {
    __shared__ float S[RANK * 34];
    const int b = blockIdx.x, tid = threadIdx.x;
    const int warp = tid >> 5, lane = tid & 31;

    if (b < 128) {
        const int is64 = sniff64(raw);
#pragma unroll
        for (int i = 0; i < 4; i++) {
            const int e = b * 1024 + i * 256 + tid;
            int k0 = get_idx(raw, e, 2, is64) * NDIM + get_idx(raw, e, 3, is64);
            int k1 = get_idx(raw, e, 4, is64) * NDIM + get_idx(raw, e, 5, is64);
            g_perm[0][atomicAdd(&g_cur[0][k0], 1)] = e;
            int pos = atomicAdd(&g_cur[1][k1], 1);
            g_perm[1][pos] = e;
            g_pos1[e] = pos;                       // inverse map for chaining
        }
    } else if (b < 192) {
        const int j0 = b - 128;
        if (tid < RANK) S[tid] = core0[j0 * RANK + tid];
        __syncthreads();
#pragma unroll
        for (int t = 0; t < 8; t++) {
            const int j1 = warp * 8 + t;
            float acc = 0.0f;
#pragma unroll
            for (int r = 0; r < RANK; r++)
                acc = fmaf(S[r], mids[r * ROW_STRIDE + j1 * RANK + lane], acc);
            g_A[(j0 * NDIM + j1) * RANK + lane] = acc;
        }
    } else if (b < 704) {
        // P1[ja,jb][r][s] = sum_m M1[r,ja,m] * M2[m,jb,s]
        const int x = b - 192;
        const int ja = x >> 3;
        const float* Ma = mids + 1 * MID_STRIDE;
        const float* Mb = mids + 2 * MID_STRIDE;

        for (int i = tid; i < RANK * RANK; i += 256) {
            int r = i >> 5, m = i & 31;
            S[m * 34 + r] = Ma[r * ROW_STRIDE + ja * RANK + m];
        }
        __syncthreads();

        const int jb = (x & 7) * 8 + warp;
        float m2[RANK];
#pragma unroll
        for (int m = 0; m < RANK; m++)
            m2[m] = Mb[m * ROW_STRIDE + jb * RANK + lane];

        ull acc2[16];
#pragma unroll
        for (int q = 0; q < 16; q++) acc2[q] = 0ull;
#pragma unroll
        for (int m = 0; m < RANK; m++) {
            const ull dup = pack2(m2[m], m2[m]);
            const ull* Sp = reinterpret_cast<const ull*>(S + m * 34);
#pragma unroll
            for (int rp = 0; rp < 16; rp++) fma2(acc2[rp], Sp[rp], dup);
        }
        float* Pp = g_P1 + (ja * NDIM + jb) * (RANK * RANK);
#pragma unroll
        for (int rp = 0; rp < 16; rp++) {
            float a, c;
            unpack2(acc2[rp], a, c);
            Pp[(2 * rp) * RANK + lane]     = a;
            Pp[(2 * rp + 1) * RANK + lane] = c;
        }
    } else {
        // Z fold: j6 = b-704; warp covers 8 j7 values
        const int j6 = b - 704;
        const float* M5 = mids + 5 * MID_STRIDE;
        for (int i = tid; i < RANK * RANK; i += 256) {
            int r = i >> 5, s = i & 31;
            S[s * 34 + r] = M5[r * ROW_STRIDE + j6 * RANK + s];
        }
        __syncthreads();
#pragma unroll
        for (int t = 0; t < 8; t++) {
            const int j7 = warp * 8 + t;
            float acc = 0.0f;
#pragma unroll
            for (int s = 0; s < RANK; s++)
                acc = fmaf(cl[s * NDIM + j7], S[s * 34 + lane], acc);
            g_Z[(j6 * NDIM + j7) * RANK + lane] = acc;
        }
    }
}

// ============================================================================
// step0m: step0 bins FIRST, then P2 fold.
// step0 writes v rows to g_vbuf in PERM1 ORDER (slot = g_pos1[e]) so step1
// reads contiguously — permutation chaining.
//   [0,4096) step0 bins      [4096,8192) P2 fold
// ============================================================================
__global__ __launch_bounds__(32)
void step0m(const int32_t* __restrict__ raw,
            const float* __restrict__ mids,
            const float* __restrict__ P1tab) {
    __shared__ __align__(16) float slice[RANK * RANK];
    __shared__ float st[RANK * 33];
    const int lane = threadIdx.x;
    const int b = blockIdx.x;

    if (b < 4096) {
        // ---------------- step0 bin (frozen inner loop) ----------------
        const int bin = b;
        const int lo = g_base[0][bin], hi = g_base[0][bin + 1];
        if (lo == hi) return;

        const float4* src4 = reinterpret_cast<const float4*>(P1tab + bin * (RANK * RANK));
        float4* dst4 = reinterpret_cast<float4*>(slice);
#pragma unroll
        for (int i = 0; i < 8; i++) dst4[i * 32 + lane] = src4[i * 32 + lane];

        const int is64 = sniff64(raw);
        __syncwarp();

        for (int base = lo; base < hi; base += 32) {
            const int n = min(32, hi - base);
            int e = 0, rowidx = 0, p1pos = 0;
            if (lane < n) {
                e = g_perm[0][base + lane];
                rowidx = get_idx(raw, e, 0, is64) * NDIM + get_idx(raw, e, 1, is64);
                p1pos = g_pos1[e];
            }
            __syncwarp();
            for (int w = 0; w < n; w++) {
                int re = __shfl_sync(0xffffffffu, rowidx, w);
                st[w * 33 + lane] = g_A[re * RANK + lane];
            }
            __syncwarp();

            ull acc[16];
#pragma unroll
            for (int q = 0; q < 16; q++) acc[q] = 0ull;
#pragma unroll 8
            for (int r = 0; r < RANK; r++) {
                float vr = st[lane * 33 + r];
                ull v2 = pack2(vr, vr);
                const ulonglong2* sp = reinterpret_cast<const ulonglong2*>(slice + r * RANK);
#pragma unroll
                for (int q = 0; q < 8; q++) {
                    ulonglong2 z = sp[q];
                    fma2(acc[2 * q],     z.x, v2);
                    fma2(acc[2 * q + 1], z.y, v2);
                }
            }

            __syncwarp();
#pragma unroll
            for (int q = 0; q < 16; q++) {
                float a, c;
                unpack2(acc[q], a, c);
                st[lane * 33 + 2 * q]     = a;
                st[lane * 33 + 2 * q + 1] = c;
            }
            __syncwarp();
            for (int w = 0; w < n; w++) {
                int pp = __shfl_sync(0xffffffffu, p1pos, w);
                g_vbuf[pp * RANK + lane] = st[w * 33 + lane];
            }
        }
    } else {
        // ---------------- P2 fold ----------------
        const int f = b - 4096;
        const int ja = f >> 6, jb = f & 63;
        const float* Ma = mids + 3 * MID_STRIDE;
        const float* Mb = mids + 4 * MID_STRIDE;

        for (int i = lane; i < RANK * RANK; i += 32) {
            int r = i >> 5, m = i & 31;
            st[m * 33 + r] = Ma[r * ROW_STRIDE + ja * RANK + m];
        }
        __syncwarp();

        float m2[RANK];
#pragma unroll
        for (int m = 0; m < RANK; m++)
            m2[m] = Mb[m * ROW_STRIDE + jb * RANK + lane];

        ull acc2[16];
#pragma unroll
        for (int q = 0; q < 16; q++) acc2[q] = 0ull;
#pragma unroll
        for (int m = 0; m < RANK; m++) {
            const ull dup = pack2(m2[m], m2[m]);
            const float* Sr = st + m * 33;
#pragma unroll
            for (int rp = 0; rp < 16; rp++) {
                ull sv = pack2(Sr[2 * rp], Sr[2 * rp + 1]);
                fma2(acc2[rp], sv, dup);
            }
        }
        float* Pp = g_P2 + (ja * NDIM + jb) * (RANK * RANK);
#pragma unroll
        for (int rp = 0; rp < 16; rp++) {
            float a, c;
            unpack2(acc2[rp], a, c);
            Pp[(2 * rp) * RANK + lane]     = a;
            Pp[(2 * rp + 1) * RANK + lane] = c;
        }
    }
}

// ============================================================================
// step1: v rows already in bin order -> contiguous coalesced loads, no shfl.
// ============================================================================
__global__ __launch_bounds__(32)
void step1_kernel(const int32_t* __restrict__ raw,
                  const float* __restrict__ P2tab, float* __restrict__ out) {
    __shared__ __align__(16) float slice[RANK * RANK];
    __shared__ float st[RANK * 33];
    const int lane = threadIdx.x;
    const int bin = blockIdx.x;
    const int lo = g_base[1][bin], hi = g_base[1][bin + 1];
    if (lo == hi) return;

    const float4* src4 = reinterpret_cast<const float4*>(P2tab + bin * (RANK * RANK));
    float4* dst4 = reinterpret_cast<float4*>(slice);
#pragma unroll
    for (int i = 0; i < 8; i++) dst4[i * 32 + lane] = src4[i * 32 + lane];

    const int is64 = sniff64(raw);
    __syncwarp();

    for (int base = lo; base < hi; base += 32) {
        const int n = min(32, hi - base);
        int e = 0;
        if (lane < n) e = g_perm[1][base + lane];

        // contiguous, in-order v load (slots [base, base+n) of g_vbuf)
        const float* vsrc = g_vbuf + (size_t)base * RANK;
        for (int w = 0; w < n; w++)
            st[w * 33 + lane] = vsrc[w * RANK + lane];
        __syncwarp();

        ull acc[16];
#pragma unroll
        for (int q = 0; q < 16; q++) acc[q] = 0ull;
#pragma unroll 8
        for (int r = 0; r < RANK; r++) {
            float vr = st[lane * 33 + r];
            ull v2 = pack2(vr, vr);
            const ulonglong2* sp = reinterpret_cast<const ulonglong2*>(slice + r * RANK);
#pragma unroll
            for (int q = 0; q < 8; q++) {
                ulonglong2 z = sp[q];
                fma2(acc[2 * q],     z.x, v2);
                fma2(acc[2 * q + 1], z.y, v2);
            }
        }

        if (lane < n) {
            int zrow = get_idx(raw, e, 6, is64) * NDIM + get_idx(raw, e, 7, is64);
            const ull* zp = reinterpret_cast<const ull*>(g_Z + zrow * RANK);
            ull d = 0ull;
#pragma unroll
            for (int q = 0; q < 16; q++) fma2(d, acc[q], zp[q]);
            float a, c;
            unpack2(d, a, c);
            out[e] = a + c;
        }
        __syncwarp();   // st WAR guard before next chunk's overwrite
    }
}

extern "C" void kernel_launch(void* const* d_in, const int* in_sizes, int n_in,
                              void* d_out, int out_size) {
    const int32_t* indices  = (const int32_t*)d_in[0];
    const float*   core0    = (const float*)d_in[1];
    const float*   coresmid = (const float*)d_in[2];
    const float*   corelast = (const float*)d_in[3];
    float*         out      = (float*)d_out;

    float* p1;  cudaGetSymbolAddress((void**)&p1, g_P1);
    float* p2;  cudaGetSymbolAddress((void**)&p2, g_P2);

    kH_hist<<<64, 256>>>(indices);
    k2_scan<<<2, 1024>>>();
    kPre<<<768, 256>>>(indices, core0, coresmid, corelast);
    step0m<<<8192, 32>>>(indices, coresmid, p1);
    step1_kernel<<<4096, 32>>>(indices, p2, out);
}